// round 16
// baseline (speedup 1.0000x reference)
#include <cuda_runtime.h>
#include <cuda_fp16.h>
#include <math.h>
#include <stdint.h>

#define SEQ    4096
#define DMODEL 1024
#define NH     16
#define HS     64

// Scratch (no cudaMalloc). fp16 copies of inputs (prepass), Q/K head-major,
// Vt transposed [h][d][tok], attn out fp16 [tok][1024].
// g_Q is pre-scaled by 0.125*log2(e) so softmax uses bare exp2.
__device__ __half g_xh[SEQ * DMODEL];
__device__ __half g_wqh[3 * DMODEL * DMODEL];
__device__ __half g_woh[DMODEL * DMODEL];
__device__ __half g_Q[NH * SEQ * HS];
__device__ __half g_K[NH * SEQ * HS];
__device__ __half g_Vt[NH * HS * SEQ];
__device__ __half g_attn[SEQ * DMODEL];

#define QSCALE 0.1803368801111244f   // 0.125 * log2(e)

__device__ __forceinline__ uint32_t packh2(float x, float y) {
    __half2 h = __float22half2_rn(make_float2(x, y));
    return *(uint32_t*)&h;
}

__device__ __forceinline__ void mma16(float* c,
    uint32_t a0, uint32_t a1, uint32_t a2, uint32_t a3,
    uint32_t b0, uint32_t b1)
{
    asm volatile(
        "mma.sync.aligned.m16n8k16.row.col.f32.f16.f16.f32 "
        "{%0,%1,%2,%3},{%4,%5,%6,%7},{%8,%9},{%0,%1,%2,%3};"
        : "+f"(c[0]), "+f"(c[1]), "+f"(c[2]), "+f"(c[3])
        : "r"(a0), "r"(a1), "r"(a2), "r"(a3), "r"(b0), "r"(b1));
}

__device__ __forceinline__ uint32_t s2u(const void* p) {
    return (uint32_t)__cvta_generic_to_shared(p);
}
__device__ __forceinline__ void ldsm4(uint32_t& r0, uint32_t& r1,
                                      uint32_t& r2, uint32_t& r3, uint32_t addr)
{
    asm volatile("ldmatrix.sync.aligned.m8n8.x4.shared.b16 {%0,%1,%2,%3}, [%4];"
                 : "=r"(r0), "=r"(r1), "=r"(r2), "=r"(r3) : "r"(addr));
}
__device__ __forceinline__ void cp16(uint32_t saddr, const void* gptr) {
    asm volatile("cp.async.cg.shared.global [%0], [%1], 16;"
                 :: "r"(saddr), "l"(gptr));
}
#define CP_COMMIT() asm volatile("cp.async.commit_group;")
#define CP_WAIT1()  asm volatile("cp.async.wait_group 1;")
#define CP_WAIT0()  asm volatile("cp.async.wait_group 0;")

// ---------------------------------------------------------------------------
// Pre-pass: fp32 -> fp16 copies of x, w_qkv, w_o.
// ---------------------------------------------------------------------------
__global__ __launch_bounds__(512) void prepass(
    const float* __restrict__ x, const float* __restrict__ wqkv,
    const float* __restrict__ wo)
{
    const int N4x = (SEQ * DMODEL) / 4;
    const int N4q = (3 * DMODEL * DMODEL) / 4;
    const int N4o = (DMODEL * DMODEL) / 4;
    const int total = N4x + N4q + N4o;
    int i = blockIdx.x * blockDim.x + threadIdx.x;
    for (; i < total; i += gridDim.x * blockDim.x) {
        const float4* src; __half* dst; int k;
        if (i < N4x)            { src = (const float4*)x;    dst = g_xh;  k = i; }
        else if (i < N4x + N4q) { src = (const float4*)wqkv; dst = g_wqh; k = i - N4x; }
        else                    { src = (const float4*)wo;   dst = g_woh; k = i - N4x - N4q; }
        float4 v = src[k];
        uint2 h;
        h.x = packh2(v.x, v.y);
        h.y = packh2(v.z, v.w);
        *(uint2*)&dst[(size_t)k * 4] = h;
    }
}

// ---------------------------------------------------------------------------
// fp16 GEMM: BK=64, 3-stage cp.async pipeline, ldmatrix fragments
// (unchanged from R14 — known-good).
// MODE 0: A = g_xh,   B = g_wqh, scatter to g_Q(scaled)/g_K/g_Vt (N = 3072)
// MODE 1: A = g_attn, B = g_woh, write fp32 C = d_out (N = 1024)
// ---------------------------------------------------------------------------
#define GSTR   36
#define GTILE  (128 * GSTR)
#define GSTAGE (2 * GTILE)
#define NSTAGE 3
#define GEMM_SMEM (NSTAGE * GSTAGE * 4)   // 110592 bytes

__device__ __forceinline__ void g_issue(uint32_t* smbase, int s,
    const __half* Asrc, const __half* Bsrc, int bm, int bn, int k0, int t)
{
    uint32_t* As = smbase + s * GSTAGE;
    uint32_t* Bs = As + GTILE;
#pragma unroll
    for (int j = 0; j < 8; j++) {
        int idx  = t + j * 256;
        int op   = idx >> 10;
        int cidx = idx & 1023;
        int row  = cidx >> 3;
        int ch   = cidx & 7;
        uint32_t* dst = (op ? Bs : As) + row * GSTR + ch * 4;
        const __half* src = (op ? Bsrc + (size_t)(bn + row) * DMODEL
                                : Asrc + (size_t)(bm + row) * DMODEL) + k0 + ch * 8;
        cp16(s2u(dst), src);
    }
    CP_COMMIT();
}

template <int MODE>
__global__ __launch_bounds__(256) void gemm_h(
    const float* __restrict__ bias, float* __restrict__ C)
{
    extern __shared__ uint32_t smg[];
    const __half* Asrc = MODE ? g_attn : g_xh;
    const __half* Bsrc = MODE ? g_woh  : g_wqh;
    const int bm = blockIdx.y * 128;
    const int bn = blockIdx.x * 128;
    const int t    = threadIdx.x;
    const int warp = t >> 5;
    const int lane = t & 31;
    const int wm = (warp >> 2) * 64;
    const int wn = (warp & 3) * 32;
    const int lr = lane >> 2;
    const int lc = lane & 3;
    const int lm16 = lane & 15;
    const int lk4  = (lane >> 4) * 4;

    float c[4][4][4];
#pragma unroll
    for (int mf = 0; mf < 4; mf++)
#pragma unroll
        for (int nf = 0; nf < 4; nf++)
#pragma unroll
            for (int r = 0; r < 4; r++) c[mf][nf][r] = 0.f;

    const int KT = DMODEL / 64;
    g_issue(smg, 0, Asrc, Bsrc, bm, bn, 0,  t);
    g_issue(smg, 1, Asrc, Bsrc, bm, bn, 64, t);

    int stage = 0;
    for (int i = 0; i < KT; i++) {
        if (i + 1 < KT) CP_WAIT1(); else CP_WAIT0();
        __syncthreads();

        if (i + 2 < KT) {
            int ns = stage + 2; if (ns >= 3) ns -= 3;
            g_issue(smg, ns, Asrc, Bsrc, bm, bn, (i + 2) * 64, t);
        }

        const uint32_t* As2 = smg + stage * GSTAGE;
        const uint32_t* Bs2 = As2 + GTILE;

#pragma unroll
        for (int kk2 = 0; kk2 < 32; kk2 += 8) {
            uint32_t a[4][4], b[4][2];
#pragma unroll
            for (int mf = 0; mf < 4; mf++)
                ldsm4(a[mf][0], a[mf][1], a[mf][2], a[mf][3],
                      s2u(&As2[(wm + mf * 16 + lm16) * GSTR + kk2 + lk4]));
#pragma unroll
            for (int nf2 = 0; nf2 < 2; nf2++) {
                uint32_t r0, r1, r2, r3;
                ldsm4(r0, r1, r2, r3,
                      s2u(&Bs2[(wn + nf2 * 16 + lm16) * GSTR + kk2 + lk4]));
                b[2 * nf2    ][0] = r0; b[2 * nf2    ][1] = r2;
                b[2 * nf2 + 1][0] = r1; b[2 * nf2 + 1][1] = r3;
            }
#pragma unroll
            for (int mf = 0; mf < 4; mf++)
#pragma unroll
                for (int nf = 0; nf < 4; nf++)
                    mma16(c[mf][nf], a[mf][0], a[mf][1], a[mf][2], a[mf][3],
                          b[nf][0], b[nf][1]);
        }
        if (++stage >= 3) stage = 0;
    }

#pragma unroll
    for (int mf = 0; mf < 4; mf++) {
#pragma unroll
        for (int nf = 0; nf < 4; nf++) {
            int n = bn + wn + nf * 8 + 2 * lc;
            float b0 = bias[n], b1 = bias[n + 1];
#pragma unroll
            for (int rh = 0; rh < 2; rh++) {
                int m = bm + wm + mf * 16 + lr + rh * 8;
                float vx = c[mf][nf][rh * 2 + 0] + b0;
                float vy = c[mf][nf][rh * 2 + 1] + b1;
                if (MODE == 0) {
                    int sel = n >> 10;
                    int nn  = n & 1023;
                    int hd  = nn >> 6;
                    int d   = nn & 63;
                    if (sel == 0) {      // Q: pre-scale for exp2 softmax
                        uint32_t h = packh2(vx * QSCALE, vy * QSCALE);
                        *(uint32_t*)&g_Q[((size_t)hd * SEQ + m) * HS + d] = h;
                    } else if (sel == 1) {
                        uint32_t h = packh2(vx, vy);
                        *(uint32_t*)&g_K[((size_t)hd * SEQ + m) * HS + d] = h;
                    } else {
                        g_Vt[((size_t)hd * HS + d    ) * SEQ + m] = __float2half_rn(vx);
                        g_Vt[((size_t)hd * HS + d + 1) * SEQ + m] = __float2half_rn(vy);
                    }
                } else {
                    float2 v; v.x = vx; v.y = vy;
                    *(float2*)&C[(size_t)m * DMODEL + n] = v;
                }
            }
        }
    }
}

// ---------------------------------------------------------------------------
// fp16 flash attention, BQ=128: 256 threads (8 warps), warp w owns q-rows
// [w*16, w*16+16) of a 128-row Q tile. Each 64x64 KV tile fill now feeds 2x
// the mma work (KV L2 traffic and smem-fill issue halved vs BQ=64).
// Register-P + ldmatrix + 2-stage cp.async KV prefetch + exp2 softmax.
// Per-warp causal bound jt_end_w = 2it + (warp>>2): barriers non-divergent,
// no fully-masked warp ever computes (NaN-safe).
// Dyn smem: Q(128x144B) + 2x{K,V}(64x144B each) = 55296 B -> 2 CTA/SM
// (reg-limited at ~120 regs; 16 warps/SM, same as R14).
// ---------------------------------------------------------------------------
#define ASTR2 36
#define ATTN_SMEM ((128 * ASTR2 + 4 * 64 * ASTR2) * 4)   // 55296 bytes

__device__ __forceinline__ void kv_issue(uint32_t* Kst, uint32_t* Vst,
    const __half* kbase, const __half* vbase, int jt, int t)
{
    const __half* kg = kbase + (size_t)jt * 64 * HS;
    const __half* vg = vbase + (size_t)jt * 64;
#pragma unroll
    for (int j = 0; j < 4; j++) {
        int idx = t + j * 256;           // 1024 chunks of 16B
        int op  = idx >> 9;              // 0 = K, 1 = V
        int c   = idx & 511;
        int row = c >> 3;
        int ch  = c & 7;
        if (op == 0)
            cp16(s2u(&Kst[row * ASTR2 + ch * 4]), kg + (size_t)row * HS + ch * 8);
        else
            cp16(s2u(&Vst[row * ASTR2 + ch * 4]), vg + (size_t)row * SEQ + ch * 8);
    }
    CP_COMMIT();
}

__global__ __launch_bounds__(256) void attn_h(const int* __restrict__ cmask)
{
    extern __shared__ uint32_t sma[];
    uint32_t* Qs2    = sma;                       // [128][ASTR2]
    uint32_t* Kst[2] = { sma + 128 * ASTR2,
                         sma + 128 * ASTR2 + 64 * ASTR2 };
    uint32_t* Vst[2] = { sma + 128 * ASTR2 + 2 * 64 * ASTR2,
                         sma + 128 * ASTR2 + 3 * 64 * ASTR2 };

    const int h   = blockIdx.y;
    const int it  = gridDim.x - 1 - blockIdx.x;   // big tiles first
    const int qi0 = it * 128;
    const int t    = threadIdx.x;
    const int warp = t >> 5;
    const int lane = t & 31;
    const int lr = lane >> 2;
    const int lc = lane & 3;
    const int w16 = warp * 16;
    const int lm16 = lane & 15;
    const int lk4  = (lane >> 4) * 4;
    const int causal = cmask ? cmask[0] : 1;

    const __half* kbase = g_K + (size_t)h * SEQ * HS;
    const __half* vbase = g_Vt + (size_t)h * HS * SEQ;
    const int jt_end_blk = causal ? 2 * it + 1 : (SEQ / 64 - 1);
    const int jt_end_w   = causal ? 2 * it + (warp >> 2) : (SEQ / 64 - 1);

    kv_issue(Kst[0], Vst[0], kbase, vbase, 0, t);   // prefetch tile 0

    {   // Q tile: 128 rows x 64 halves (overlaps with cp.async in flight)
        const __half* src = g_Q + ((size_t)h * SEQ + qi0) * HS;
#pragma unroll
        for (int j = 0; j < 4; j++) {
            int idx = t + j * 256;       // 1024 uint4 chunks
            int row = idx >> 3;
            int col = (idx & 7) * 8;
            *(uint4*)&Qs2[row * ASTR2 + col / 2] =
                *(const uint4*)(src + (size_t)row * HS + col);
        }
    }

    float mrow0 = -INFINITY, mrow1 = -INFINITY, l0 = 0.f, l1 = 0.f;
    float O[8][4];
#pragma unroll
    for (int nf = 0; nf < 8; nf++)
#pragma unroll
        for (int r = 0; r < 4; r++) O[nf][r] = 0.f;

    for (int jt = 0; jt <= jt_end_blk; jt++) {
        const int s = jt & 1;
        __syncthreads();                 // all warps done with stage s^1
        if (jt < jt_end_blk) {
            kv_issue(Kst[s ^ 1], Vst[s ^ 1], kbase, vbase, jt + 1, t);
            CP_WAIT1();
        } else {
            CP_WAIT0();
        }
        __syncthreads();                 // stage s visible to all warps

        if (jt <= jt_end_w) {
            const uint32_t* Ks2 = Kst[s];
            const uint32_t* Vs2 = Vst[s];

            // ---- S' = (Q*0.125*log2e) K^T ----
            float c[8][4];
#pragma unroll
            for (int nf = 0; nf < 8; nf++)
#pragma unroll
                for (int r = 0; r < 4; r++) c[nf][r] = 0.f;

#pragma unroll
            for (int kk2 = 0; kk2 < 32; kk2 += 8) {
                uint32_t a0, a1, a2, a3;
                ldsm4(a0, a1, a2, a3,
                      s2u(&Qs2[(w16 + lm16) * ASTR2 + kk2 + lk4]));
#pragma unroll
                for (int nf2 = 0; nf2 < 4; nf2++) {
                    uint32_t r0, r1, r2, r3;
                    ldsm4(r0, r1, r2, r3,
                          s2u(&Ks2[(nf2 * 16 + lm16) * ASTR2 + kk2 + lk4]));
                    mma16(c[2 * nf2    ], a0, a1, a2, a3, r0, r2);
                    mma16(c[2 * nf2 + 1], a0, a1, a2, a3, r1, r3);
                }
            }

            // ---- causal mask (scale folded into Q) ----
            const bool diag = causal && (jt * 64 + 63 > qi0 + w16);
            if (diag) {
                const int row0 = qi0 + w16 + lr;
                const int row1 = row0 + 8;
#pragma unroll
                for (int nf = 0; nf < 8; nf++) {
                    int col = jt * 64 + nf * 8 + 2 * lc;
                    if (col     > row0) c[nf][0] = -INFINITY;
                    if (col + 1 > row0) c[nf][1] = -INFINITY;
                    if (col     > row1) c[nf][2] = -INFINITY;
                    if (col + 1 > row1) c[nf][3] = -INFINITY;
                }
            }

            // ---- online softmax in log2 domain ----
            float mx0 = -INFINITY, mx1 = -INFINITY;
#pragma unroll
            for (int nf = 0; nf < 8; nf++) {
                mx0 = fmaxf(mx0, fmaxf(c[nf][0], c[nf][1]));
                mx1 = fmaxf(mx1, fmaxf(c[nf][2], c[nf][3]));
            }
            mx0 = fmaxf(mx0, __shfl_xor_sync(0xffffffffu, mx0, 1));
            mx0 = fmaxf(mx0, __shfl_xor_sync(0xffffffffu, mx0, 2));
            mx1 = fmaxf(mx1, __shfl_xor_sync(0xffffffffu, mx1, 1));
            mx1 = fmaxf(mx1, __shfl_xor_sync(0xffffffffu, mx1, 2));

            const float mn0 = fmaxf(mrow0, mx0);
            const float mn1 = fmaxf(mrow1, mx1);
            const float al0 = exp2f(mrow0 - mn0);
            const float al1 = exp2f(mrow1 - mn1);
            float s0 = 0.f, s1 = 0.f;
#pragma unroll
            for (int nf = 0; nf < 8; nf++) {
                c[nf][0] = exp2f(c[nf][0] - mn0); s0 += c[nf][0];
                c[nf][1] = exp2f(c[nf][1] - mn0); s0 += c[nf][1];
                c[nf][2] = exp2f(c[nf][2] - mn1); s1 += c[nf][2];
                c[nf][3] = exp2f(c[nf][3] - mn1); s1 += c[nf][3];
            }
            s0 += __shfl_xor_sync(0xffffffffu, s0, 1);
            s0 += __shfl_xor_sync(0xffffffffu, s0, 2);
            s1 += __shfl_xor_sync(0xffffffffu, s1, 1);
            s1 += __shfl_xor_sync(0xffffffffu, s1, 2);
            l0 = l0 * al0 + s0;  l1 = l1 * al1 + s1;
            mrow0 = mn0;         mrow1 = mn1;
#pragma unroll
            for (int nf = 0; nf < 8; nf++) {
                O[nf][0] *= al0; O[nf][1] *= al0;
                O[nf][2] *= al1; O[nf][3] *= al1;
            }

            // ---- O += P V, P straight from registers ----
#pragma unroll
            for (int k2 = 0; k2 < 4; k2++) {
                uint32_t a0 = packh2(c[2 * k2    ][0], c[2 * k2    ][1]);
                uint32_t a1 = packh2(c[2 * k2    ][2], c[2 * k2    ][3]);
                uint32_t a2 = packh2(c[2 * k2 + 1][0], c[2 * k2 + 1][1]);
                uint32_t a3 = packh2(c[2 * k2 + 1][2], c[2 * k2 + 1][3]);
#pragma unroll
                for (int nf2 = 0; nf2 < 4; nf2++) {
                    uint32_t r0, r1, r2, r3;
                    ldsm4(r0, r1, r2, r3,
                          s2u(&Vs2[(nf2 * 16 + lm16) * ASTR2 + 8 * k2 + lk4]));
                    mma16(O[2 * nf2    ], a0, a1, a2, a3, r0, r2);
                    mma16(O[2 * nf2 + 1], a0, a1, a2, a3, r1, r3);
                }
            }
        }
    }

    // ---- epilogue: normalize, write fp16 to g_attn ----
    const float inv0 = 1.f / l0;
    const float inv1 = 1.f / l1;
#pragma unroll
    for (int nf = 0; nf < 8; nf++) {
        int col = h * HS + nf * 8 + 2 * lc;
        *(uint32_t*)&g_attn[(size_t)(qi0 + w16 + lr    ) * DMODEL + col] =
            packh2(O[nf][0] * inv0, O[nf][1] * inv0);
        *(uint32_t*)&g_attn[(size_t)(qi0 + w16 + lr + 8) * DMODEL + col] =
            packh2(O[nf][2] * inv1, O[nf][3] * inv1);
    }
}

// ---------------------------------------------------------------------------
extern "C" void kernel_launch(void* const* d_in, const int* in_sizes, int n_in,
                              void* d_out, int out_size)
{
    const float* x     = (const float*)d_in[0];
    const float* w_qkv = (const float*)d_in[1];
    const float* b_qkv = (const float*)d_in[2];
    const float* w_o   = (const float*)d_in[3];
    const float* b_o   = (const float*)d_in[4];
    const int*   cmask = (n_in > 5) ? (const int*)d_in[5] : nullptr;

    cudaFuncSetAttribute(gemm_h<0>,
                         cudaFuncAttributeMaxDynamicSharedMemorySize, GEMM_SMEM);
    cudaFuncSetAttribute(gemm_h<1>,
                         cudaFuncAttributeMaxDynamicSharedMemorySize, GEMM_SMEM);
    cudaFuncSetAttribute(attn_h,
                         cudaFuncAttributeMaxDynamicSharedMemorySize, ATTN_SMEM);

    prepass<<<1024, 512>>>(x, w_qkv, w_o);
    gemm_h<0><<<dim3(3072 / 128, SEQ / 128), 256, GEMM_SMEM>>>(b_qkv, nullptr);
    attn_h<<<dim3(SEQ / 128, NH), 256, ATTN_SMEM>>>(cmask);
    gemm_h<1><<<dim3(DMODEL / 128, SEQ / 128), 256, GEMM_SMEM>>>(b_o,
                                                                 (float*)d_out);
}

// round 17
// speedup vs baseline: 1.0697x; 1.0697x over previous
#include <cuda_runtime.h>
#include <cuda_fp16.h>
#include <math.h>
#include <stdint.h>

#define SEQ    4096
#define DMODEL 1024
#define NH     16
#define HS     64

// Scratch (no cudaMalloc). fp16 copies of inputs (prepass), Q/K head-major,
// Vt transposed [h][d][tok], attn out fp16 [tok][1024].
// g_Q is pre-scaled by 0.125*log2(e) so softmax uses bare exp2.
__device__ __half g_xh[SEQ * DMODEL];
__device__ __half g_wqh[3 * DMODEL * DMODEL];
__device__ __half g_woh[DMODEL * DMODEL];
__device__ __half g_Q[NH * SEQ * HS];
__device__ __half g_K[NH * SEQ * HS];
__device__ __half g_Vt[NH * HS * SEQ];
__device__ __half g_attn[SEQ * DMODEL];

#define QSCALE 0.1803368801111244f   // 0.125 * log2(e)

__device__ __forceinline__ uint32_t packh2(float x, float y) {
    __half2 h = __float22half2_rn(make_float2(x, y));
    return *(uint32_t*)&h;
}

__device__ __forceinline__ void mma16(float* c,
    uint32_t a0, uint32_t a1, uint32_t a2, uint32_t a3,
    uint32_t b0, uint32_t b1)
{
    asm volatile(
        "mma.sync.aligned.m16n8k16.row.col.f32.f16.f16.f32 "
        "{%0,%1,%2,%3},{%4,%5,%6,%7},{%8,%9},{%0,%1,%2,%3};"
        : "+f"(c[0]), "+f"(c[1]), "+f"(c[2]), "+f"(c[3])
        : "r"(a0), "r"(a1), "r"(a2), "r"(a3), "r"(b0), "r"(b1));
}

__device__ __forceinline__ uint32_t s2u(const void* p) {
    return (uint32_t)__cvta_generic_to_shared(p);
}
__device__ __forceinline__ void ldsm4(uint32_t& r0, uint32_t& r1,
                                      uint32_t& r2, uint32_t& r3, uint32_t addr)
{
    asm volatile("ldmatrix.sync.aligned.m8n8.x4.shared.b16 {%0,%1,%2,%3}, [%4];"
                 : "=r"(r0), "=r"(r1), "=r"(r2), "=r"(r3) : "r"(addr));
}
__device__ __forceinline__ void cp16(uint32_t saddr, const void* gptr) {
    asm volatile("cp.async.cg.shared.global [%0], [%1], 16;"
                 :: "r"(saddr), "l"(gptr));
}
#define CP_COMMIT() asm volatile("cp.async.commit_group;")
#define CP_WAIT1()  asm volatile("cp.async.wait_group 1;")
#define CP_WAIT0()  asm volatile("cp.async.wait_group 0;")

// ---------------------------------------------------------------------------
// Pre-pass: fp32 -> fp16 copies of x, w_qkv, w_o.
// ---------------------------------------------------------------------------
__global__ __launch_bounds__(512) void prepass(
    const float* __restrict__ x, const float* __restrict__ wqkv,
    const float* __restrict__ wo)
{
    const int N4x = (SEQ * DMODEL) / 4;
    const int N4q = (3 * DMODEL * DMODEL) / 4;
    const int N4o = (DMODEL * DMODEL) / 4;
    const int total = N4x + N4q + N4o;
    int i = blockIdx.x * blockDim.x + threadIdx.x;
    for (; i < total; i += gridDim.x * blockDim.x) {
        const float4* src; __half* dst; int k;
        if (i < N4x)            { src = (const float4*)x;    dst = g_xh;  k = i; }
        else if (i < N4x + N4q) { src = (const float4*)wqkv; dst = g_wqh; k = i - N4x; }
        else                    { src = (const float4*)wo;   dst = g_woh; k = i - N4x - N4q; }
        float4 v = src[k];
        uint2 h;
        h.x = packh2(v.x, v.y);
        h.y = packh2(v.z, v.w);
        *(uint2*)&dst[(size_t)k * 4] = h;
    }
}

// ---------------------------------------------------------------------------
// fp16 GEMM: BK=64, 3-stage cp.async pipeline, ldmatrix fragments
// (unchanged from R14 — known-good).
// MODE 0: A = g_xh,   B = g_wqh, scatter to g_Q(scaled)/g_K/g_Vt (N = 3072)
// MODE 1: A = g_attn, B = g_woh, write fp32 C = d_out (N = 1024)
// ---------------------------------------------------------------------------
#define GSTR   36
#define GTILE  (128 * GSTR)
#define GSTAGE (2 * GTILE)
#define NSTAGE 3
#define GEMM_SMEM (NSTAGE * GSTAGE * 4)   // 110592 bytes

__device__ __forceinline__ void g_issue(uint32_t* smbase, int s,
    const __half* Asrc, const __half* Bsrc, int bm, int bn, int k0, int t)
{
    uint32_t* As = smbase + s * GSTAGE;
    uint32_t* Bs = As + GTILE;
#pragma unroll
    for (int j = 0; j < 8; j++) {
        int idx  = t + j * 256;
        int op   = idx >> 10;
        int cidx = idx & 1023;
        int row  = cidx >> 3;
        int ch   = cidx & 7;
        uint32_t* dst = (op ? Bs : As) + row * GSTR + ch * 4;
        const __half* src = (op ? Bsrc + (size_t)(bn + row) * DMODEL
                                : Asrc + (size_t)(bm + row) * DMODEL) + k0 + ch * 8;
        cp16(s2u(dst), src);
    }
    CP_COMMIT();
}

template <int MODE>
__global__ __launch_bounds__(256) void gemm_h(
    const float* __restrict__ bias, float* __restrict__ C)
{
    extern __shared__ uint32_t smg[];
    const __half* Asrc = MODE ? g_attn : g_xh;
    const __half* Bsrc = MODE ? g_woh  : g_wqh;
    const int bm = blockIdx.y * 128;
    const int bn = blockIdx.x * 128;
    const int t    = threadIdx.x;
    const int warp = t >> 5;
    const int lane = t & 31;
    const int wm = (warp >> 2) * 64;
    const int wn = (warp & 3) * 32;
    const int lr = lane >> 2;
    const int lc = lane & 3;
    const int lm16 = lane & 15;
    const int lk4  = (lane >> 4) * 4;

    float c[4][4][4];
#pragma unroll
    for (int mf = 0; mf < 4; mf++)
#pragma unroll
        for (int nf = 0; nf < 4; nf++)
#pragma unroll
            for (int r = 0; r < 4; r++) c[mf][nf][r] = 0.f;

    const int KT = DMODEL / 64;
    g_issue(smg, 0, Asrc, Bsrc, bm, bn, 0,  t);
    g_issue(smg, 1, Asrc, Bsrc, bm, bn, 64, t);

    int stage = 0;
    for (int i = 0; i < KT; i++) {
        if (i + 1 < KT) CP_WAIT1(); else CP_WAIT0();
        __syncthreads();

        if (i + 2 < KT) {
            int ns = stage + 2; if (ns >= 3) ns -= 3;
            g_issue(smg, ns, Asrc, Bsrc, bm, bn, (i + 2) * 64, t);
        }

        const uint32_t* As2 = smg + stage * GSTAGE;
        const uint32_t* Bs2 = As2 + GTILE;

#pragma unroll
        for (int kk2 = 0; kk2 < 32; kk2 += 8) {
            uint32_t a[4][4], b[4][2];
#pragma unroll
            for (int mf = 0; mf < 4; mf++)
                ldsm4(a[mf][0], a[mf][1], a[mf][2], a[mf][3],
                      s2u(&As2[(wm + mf * 16 + lm16) * GSTR + kk2 + lk4]));
#pragma unroll
            for (int nf2 = 0; nf2 < 2; nf2++) {
                uint32_t r0, r1, r2, r3;
                ldsm4(r0, r1, r2, r3,
                      s2u(&Bs2[(wn + nf2 * 16 + lm16) * GSTR + kk2 + lk4]));
                b[2 * nf2    ][0] = r0; b[2 * nf2    ][1] = r2;
                b[2 * nf2 + 1][0] = r1; b[2 * nf2 + 1][1] = r3;
            }
#pragma unroll
            for (int mf = 0; mf < 4; mf++)
#pragma unroll
                for (int nf = 0; nf < 4; nf++)
                    mma16(c[mf][nf], a[mf][0], a[mf][1], a[mf][2], a[mf][3],
                          b[nf][0], b[nf][1]);
        }
        if (++stage >= 3) stage = 0;
    }

#pragma unroll
    for (int mf = 0; mf < 4; mf++) {
#pragma unroll
        for (int nf = 0; nf < 4; nf++) {
            int n = bn + wn + nf * 8 + 2 * lc;
            float b0 = bias[n], b1 = bias[n + 1];
#pragma unroll
            for (int rh = 0; rh < 2; rh++) {
                int m = bm + wm + mf * 16 + lr + rh * 8;
                float vx = c[mf][nf][rh * 2 + 0] + b0;
                float vy = c[mf][nf][rh * 2 + 1] + b1;
                if (MODE == 0) {
                    int sel = n >> 10;
                    int nn  = n & 1023;
                    int hd  = nn >> 6;
                    int d   = nn & 63;
                    if (sel == 0) {      // Q: pre-scale for exp2 softmax
                        uint32_t h = packh2(vx * QSCALE, vy * QSCALE);
                        *(uint32_t*)&g_Q[((size_t)hd * SEQ + m) * HS + d] = h;
                    } else if (sel == 1) {
                        uint32_t h = packh2(vx, vy);
                        *(uint32_t*)&g_K[((size_t)hd * SEQ + m) * HS + d] = h;
                    } else {
                        g_Vt[((size_t)hd * HS + d    ) * SEQ + m] = __float2half_rn(vx);
                        g_Vt[((size_t)hd * HS + d + 1) * SEQ + m] = __float2half_rn(vy);
                    }
                } else {
                    float2 v; v.x = vx; v.y = vy;
                    *(float2*)&C[(size_t)m * DMODEL + n] = v;
                }
            }
        }
    }
}

// ---------------------------------------------------------------------------
// fp16 flash attention, BQ=64 (reverted from R16's BQ=128 regression),
// now with a 3-stage KV pipeline and ONE __syncthreads per tile (same
// transformation as the GEMM mainloop: after the top-of-iter barrier, all
// warps have finished compute of iter jt-1, so issuing into stage
// (jt+2)%3 == (jt-1)%3 is safe).
// Register-P + ldmatrix + exp2 softmax. Grid (S/64, NH), 128 threads.
// Dyn smem: Q + 3x{K,V} = 63 KB -> 3 CTA/SM (12 warps; R6 measured 12 vs 16
// warps as ~neutral, so the barrier saving should dominate).
// ---------------------------------------------------------------------------
#define ASTR2 36
#define KVT (64 * ASTR2)                       // u32 per K (or V) tile
#define ATTN_SMEM ((KVT + 6 * KVT) * 4)        // 64512 bytes

__device__ __forceinline__ void kv_issue(uint32_t* sma, int s,
    const __half* kbase, const __half* vbase, int jt, int t)
{
    uint32_t* Kst = sma + KVT * (1 + 2 * s);
    uint32_t* Vst = sma + KVT * (2 + 2 * s);
    const __half* kg = kbase + (size_t)jt * 64 * HS;
    const __half* vg = vbase + (size_t)jt * 64;
#pragma unroll
    for (int j = 0; j < 8; j++) {
        int idx = t + j * 128;           // 1024 chunks of 16B
        int op  = idx >> 9;              // 0 = K, 1 = V
        int c   = idx & 511;
        int row = c >> 3;
        int ch  = c & 7;
        if (op == 0)
            cp16(s2u(&Kst[row * ASTR2 + ch * 4]), kg + (size_t)row * HS + ch * 8);
        else
            cp16(s2u(&Vst[row * ASTR2 + ch * 4]), vg + (size_t)row * SEQ + ch * 8);
    }
    CP_COMMIT();
}

__global__ __launch_bounds__(128) void attn_h(const int* __restrict__ cmask)
{
    extern __shared__ uint32_t sma[];
    uint32_t* Qs2 = sma;                 // [64][ASTR2]

    const int h   = blockIdx.y;
    const int it  = gridDim.x - 1 - blockIdx.x;   // big tiles first
    const int qi0 = it * 64;
    const int t    = threadIdx.x;
    const int warp = t >> 5;
    const int lane = t & 31;
    const int lr = lane >> 2;
    const int lc = lane & 3;
    const int w16 = warp * 16;
    const int lm16 = lane & 15;
    const int lk4  = (lane >> 4) * 4;
    const int causal = cmask ? cmask[0] : 1;

    const __half* kbase = g_K + (size_t)h * SEQ * HS;
    const __half* vbase = g_Vt + (size_t)h * HS * SEQ;
    const int jt_end = causal ? it : (SEQ / 64 - 1);

    kv_issue(sma, 0, kbase, vbase, 0, t);             // prefetch tile 0
    if (jt_end >= 1) kv_issue(sma, 1, kbase, vbase, 1, t);

    {   // Q tile (overlaps with cp.async in flight)
        const __half* src = g_Q + ((size_t)h * SEQ + qi0) * HS;
#pragma unroll
        for (int j = 0; j < 4; j++) {
            int idx = t + j * 128;
            int row = idx >> 3;
            int col = (idx & 7) * 8;
            *(uint4*)&Qs2[row * ASTR2 + col / 2] =
                *(const uint4*)(src + (size_t)row * HS + col);
        }
    }

    float mrow0 = -INFINITY, mrow1 = -INFINITY, l0 = 0.f, l1 = 0.f;
    float O[8][4];
#pragma unroll
    for (int nf = 0; nf < 8; nf++)
#pragma unroll
        for (int r = 0; r < 4; r++) O[nf][r] = 0.f;

    int stage = 0;
    for (int jt = 0; jt <= jt_end; jt++) {
        if (jt + 1 <= jt_end) CP_WAIT1(); else CP_WAIT0();
        __syncthreads();                 // compute(jt-1) done + stage jt visible

        if (jt + 2 <= jt_end) {          // into stage consumed at jt-1
            int ns = stage + 2; if (ns >= 3) ns -= 3;
            kv_issue(sma, ns, kbase, vbase, jt + 2, t);
        }

        const uint32_t* Ks2 = sma + KVT * (1 + 2 * stage);
        const uint32_t* Vs2 = sma + KVT * (2 + 2 * stage);

        // ---- S' = (Q*0.125*log2e) K^T ----
        float c[8][4];
#pragma unroll
        for (int nf = 0; nf < 8; nf++)
#pragma unroll
            for (int r = 0; r < 4; r++) c[nf][r] = 0.f;

#pragma unroll
        for (int kk2 = 0; kk2 < 32; kk2 += 8) {
            uint32_t a0, a1, a2, a3;
            ldsm4(a0, a1, a2, a3,
                  s2u(&Qs2[(w16 + lm16) * ASTR2 + kk2 + lk4]));
#pragma unroll
            for (int nf2 = 0; nf2 < 4; nf2++) {
                uint32_t r0, r1, r2, r3;
                ldsm4(r0, r1, r2, r3,
                      s2u(&Ks2[(nf2 * 16 + lm16) * ASTR2 + kk2 + lk4]));
                mma16(c[2 * nf2    ], a0, a1, a2, a3, r0, r2);
                mma16(c[2 * nf2 + 1], a0, a1, a2, a3, r1, r3);
            }
        }

        // ---- causal mask (scale folded into Q) ----
        const bool diag = causal && (jt == it);
        if (diag) {
            const int row0 = qi0 + w16 + lr;
            const int row1 = row0 + 8;
#pragma unroll
            for (int nf = 0; nf < 8; nf++) {
                int col = jt * 64 + nf * 8 + 2 * lc;
                if (col     > row0) c[nf][0] = -INFINITY;
                if (col + 1 > row0) c[nf][1] = -INFINITY;
                if (col     > row1) c[nf][2] = -INFINITY;
                if (col + 1 > row1) c[nf][3] = -INFINITY;
            }
        }

        // ---- online softmax in log2 domain ----
        float mx0 = -INFINITY, mx1 = -INFINITY;
#pragma unroll
        for (int nf = 0; nf < 8; nf++) {
            mx0 = fmaxf(mx0, fmaxf(c[nf][0], c[nf][1]));
            mx1 = fmaxf(mx1, fmaxf(c[nf][2], c[nf][3]));
        }
        mx0 = fmaxf(mx0, __shfl_xor_sync(0xffffffffu, mx0, 1));
        mx0 = fmaxf(mx0, __shfl_xor_sync(0xffffffffu, mx0, 2));
        mx1 = fmaxf(mx1, __shfl_xor_sync(0xffffffffu, mx1, 1));
        mx1 = fmaxf(mx1, __shfl_xor_sync(0xffffffffu, mx1, 2));

        const float mn0 = fmaxf(mrow0, mx0);
        const float mn1 = fmaxf(mrow1, mx1);
        const float al0 = exp2f(mrow0 - mn0);
        const float al1 = exp2f(mrow1 - mn1);
        float s0 = 0.f, s1 = 0.f;
#pragma unroll
        for (int nf = 0; nf < 8; nf++) {
            c[nf][0] = exp2f(c[nf][0] - mn0); s0 += c[nf][0];
            c[nf][1] = exp2f(c[nf][1] - mn0); s0 += c[nf][1];
            c[nf][2] = exp2f(c[nf][2] - mn1); s1 += c[nf][2];
            c[nf][3] = exp2f(c[nf][3] - mn1); s1 += c[nf][3];
        }
        s0 += __shfl_xor_sync(0xffffffffu, s0, 1);
        s0 += __shfl_xor_sync(0xffffffffu, s0, 2);
        s1 += __shfl_xor_sync(0xffffffffu, s1, 1);
        s1 += __shfl_xor_sync(0xffffffffu, s1, 2);
        l0 = l0 * al0 + s0;  l1 = l1 * al1 + s1;
        mrow0 = mn0;         mrow1 = mn1;
#pragma unroll
        for (int nf = 0; nf < 8; nf++) {
            O[nf][0] *= al0; O[nf][1] *= al0;
            O[nf][2] *= al1; O[nf][3] *= al1;
        }

        // ---- O += P V, P straight from registers ----
#pragma unroll
        for (int k2 = 0; k2 < 4; k2++) {
            uint32_t a0 = packh2(c[2 * k2    ][0], c[2 * k2    ][1]);
            uint32_t a1 = packh2(c[2 * k2    ][2], c[2 * k2    ][3]);
            uint32_t a2 = packh2(c[2 * k2 + 1][0], c[2 * k2 + 1][1]);
            uint32_t a3 = packh2(c[2 * k2 + 1][2], c[2 * k2 + 1][3]);
#pragma unroll
            for (int nf2 = 0; nf2 < 4; nf2++) {
                uint32_t r0, r1, r2, r3;
                ldsm4(r0, r1, r2, r3,
                      s2u(&Vs2[(nf2 * 16 + lm16) * ASTR2 + 8 * k2 + lk4]));
                mma16(O[2 * nf2    ], a0, a1, a2, a3, r0, r2);
                mma16(O[2 * nf2 + 1], a0, a1, a2, a3, r1, r3);
            }
        }

        if (++stage >= 3) stage = 0;
    }

    // ---- epilogue: normalize, write fp16 to g_attn ----
    const float inv0 = 1.f / l0;
    const float inv1 = 1.f / l1;
#pragma unroll
    for (int nf = 0; nf < 8; nf++) {
        int col = h * HS + nf * 8 + 2 * lc;
        *(uint32_t*)&g_attn[(size_t)(qi0 + w16 + lr    ) * DMODEL + col] =
            packh2(O[nf][0] * inv0, O[nf][1] * inv0);
        *(uint32_t*)&g_attn[(size_t)(qi0 + w16 + lr + 8) * DMODEL + col] =
            packh2(O[nf][2] * inv1, O[nf][3] * inv1);
    }
}

// ---------------------------------------------------------------------------
extern "C" void kernel_launch(void* const* d_in, const int* in_sizes, int n_in,
                              void* d_out, int out_size)
{
    const float* x     = (const float*)d_in[0];
    const float* w_qkv = (const float*)d_in[1];
    const float* b_qkv = (const float*)d_in[2];
    const float* w_o   = (const float*)d_in[3];
    const float* b_o   = (const float*)d_in[4];
    const int*   cmask = (n_in > 5) ? (const int*)d_in[5] : nullptr;

    cudaFuncSetAttribute(gemm_h<0>,
                         cudaFuncAttributeMaxDynamicSharedMemorySize, GEMM_SMEM);
    cudaFuncSetAttribute(gemm_h<1>,
                         cudaFuncAttributeMaxDynamicSharedMemorySize, GEMM_SMEM);
    cudaFuncSetAttribute(attn_h,
                         cudaFuncAttributeMaxDynamicSharedMemorySize, ATTN_SMEM);

    prepass<<<1024, 512>>>(x, w_qkv, w_o);
    gemm_h<0><<<dim3(3072 / 128, SEQ / 128), 256, GEMM_SMEM>>>(b_qkv, nullptr);
    attn_h<<<dim3(SEQ / 64, NH), 128, ATTN_SMEM>>>(cmask);
    gemm_h<1><<<dim3(DMODEL / 128, SEQ / 128), 256, GEMM_SMEM>>>(b_o,
                                                                 (float*)d_out);
}